// round 9
// baseline (speedup 1.0000x reference)
#include <cuda_runtime.h>
#include <math.h>

// ---------------- problem constants ----------------
constexpr int N_EMBD = 2048;
constexpr int NHEAD  = 16;
constexpr int HDIM   = 128;
constexpr int BATCH  = 2;
constexpr int SEQ    = 2048;
constexpr int ROWS   = BATCH * SEQ;   // 4096

// ---------------- scratch (device globals: no allocs allowed) ----------------
__device__ float g_q[ROWS * N_EMBD];
__device__ float g_k[ROWS * N_EMBD];
__device__ float g_v[ROWS * N_EMBD];
__device__ float g_y[ROWS * N_EMBD];

// =====================================================================
// SGEMM: C[M,N] = A[M,K] @ B[K,N], all row-major, M,N,K % 128 == 0
// 128x128 block tile, BK=8, 256 threads, 8x8 register micro-tile.
// =====================================================================
__global__ __launch_bounds__(256) void sgemm_kernel(
    const float* __restrict__ A, const float* __restrict__ B,
    float* __restrict__ C, int M, int N, int K)
{
    __shared__ float As[8][128];   // As[k][m] (transposed A tile)
    __shared__ float Bs[8][132];   // Bs[k][n] (padded)

    const int tid  = threadIdx.x;
    const int row0 = blockIdx.y * 128;
    const int col0 = blockIdx.x * 128;

    const int aRow = tid >> 1;          // 0..127
    const int aCol = (tid & 1) * 4;     // 0 or 4
    const int bRow = tid >> 5;          // 0..7
    const int bCol = (tid & 31) * 4;    // 0..124

    const int tx = tid & 15;
    const int ty = tid >> 4;

    float acc[8][8];
#pragma unroll
    for (int i = 0; i < 8; i++)
#pragma unroll
        for (int j = 0; j < 8; j++) acc[i][j] = 0.f;

    const float* Ap = A + (size_t)(row0 + aRow) * K + aCol;
    const float* Bp = B + (size_t)col0 + bCol;

    for (int k0 = 0; k0 < K; k0 += 8) {
        float4 av = *(const float4*)(Ap + k0);
        float4 bv = *(const float4*)(Bp + (size_t)(k0 + bRow) * N);
        __syncthreads();
        As[aCol + 0][aRow] = av.x;
        As[aCol + 1][aRow] = av.y;
        As[aCol + 2][aRow] = av.z;
        As[aCol + 3][aRow] = av.w;
        *(float4*)&Bs[bRow][bCol] = bv;
        __syncthreads();

#pragma unroll
        for (int kk = 0; kk < 8; kk++) {
            float4 a0 = *(const float4*)&As[kk][ty * 8];
            float4 a1 = *(const float4*)&As[kk][ty * 8 + 4];
            float4 b0 = *(const float4*)&Bs[kk][tx * 8];
            float4 b1 = *(const float4*)&Bs[kk][tx * 8 + 4];
            float a[8] = {a0.x, a0.y, a0.z, a0.w, a1.x, a1.y, a1.z, a1.w};
            float b[8] = {b0.x, b0.y, b0.z, b0.w, b1.x, b1.y, b1.z, b1.w};
#pragma unroll
            for (int i = 0; i < 8; i++)
#pragma unroll
                for (int j = 0; j < 8; j++)
                    acc[i][j] = fmaf(a[i], b[j], acc[i][j]);
        }
    }

#pragma unroll
    for (int i = 0; i < 8; i++) {
        float* Cp = C + (size_t)(row0 + ty * 8 + i) * N + col0 + tx * 8;
        *(float4*)Cp       = make_float4(acc[i][0], acc[i][1], acc[i][2], acc[i][3]);
        *(float4*)(Cp + 4) = make_float4(acc[i][4], acc[i][5], acc[i][6], acc[i][7]);
    }
}

// =====================================================================
// RoPE (interleaved pairs, applied in-place to q and k)
// =====================================================================
__global__ void rope_kernel(float* __restrict__ q, float* __restrict__ k)
{
    int idx = blockIdx.x * blockDim.x + threadIdx.x;
    if (idx >= ROWS * (N_EMBD / 2)) return;
    int row = idx >> 10;            // 1024 pairs per row
    int p   = idx & 1023;           // pair index in row: h*64 + i
    int i   = p & 63;               // pair within head
    int s   = row & (SEQ - 1);      // sequence position

    // inv_freq = 10000^(-i/64) ; ln(10000)/64 = 0.14391156831212787
    float inv = expf(-(float)i * 0.14391156831212787f);
    float ang = (float)s * inv;
    float sn, c;
    sincosf(ang, &sn, &c);

    int base = row * N_EMBD + (p << 1);
    float q1 = q[base], q2 = q[base + 1];
    q[base]     = q1 * c - q2 * sn;
    q[base + 1] = q1 * sn + q2 * c;
    float k1 = k[base], k2 = k[base + 1];
    k[base]     = k1 * c - k2 * sn;
    k[base + 1] = k1 * sn + k2 * c;
}

// =====================================================================
// Fused causal attention (flash-style, fp32).
// Block = 256 threads handles one (b, h, 64-query tile).
// Online softmax stats kept in registers (each row owned by 16 lanes).
// K and V share one smem buffer (loaded sequentially per key tile).
// =====================================================================
constexpr int BQ = 64, BKT = 64;
constexpr int QS_STRIDE = 129;   // odd-mod-8 stride -> low LDS conflicts for column reads
constexpr int KS_STRIDE = 129;
constexpr int VS_STRIDE = 132;   // float4-aligned rows
constexpr int PS_STRIDE = 65;
constexpr int ATTN_SMEM_FLOATS = BQ * QS_STRIDE + BQ * VS_STRIDE + BQ * PS_STRIDE;
constexpr int ATTN_SMEM_BYTES  = ATTN_SMEM_FLOATS * 4;   // 83456 B

__global__ __launch_bounds__(256) void attn_kernel()
{
    extern __shared__ float sm[];
    float* Qs = sm;
    float* KV = Qs + BQ * QS_STRIDE;
    float* Ps = KV + BQ * VS_STRIDE;

    const int qt = blockIdx.x, h = blockIdx.y, b = blockIdx.z;
    const int tid = threadIdx.x;
    const int tx = tid & 15;    // 16 lanes share a row group
    const int ty = tid >> 4;    // owns query rows ty*4 .. ty*4+3
    const float scale = 0.08838834764831845f;  // 1/sqrt(128)

    // load Q tile (pre-scaled)
    const float* qg = g_q + (size_t)(b * SEQ + qt * BQ) * N_EMBD + h * HDIM;
    for (int t = tid; t < BQ * 32; t += 256) {
        int r = t >> 5, c = (t & 31) * 4;
        float4 v = *(const float4*)(qg + (size_t)r * N_EMBD + c);
        float* d = Qs + r * QS_STRIDE + c;
        d[0] = v.x * scale; d[1] = v.y * scale; d[2] = v.z * scale; d[3] = v.w * scale;
    }

    float o[4][8];
#pragma unroll
    for (int i = 0; i < 4; i++)
#pragma unroll
        for (int j = 0; j < 8; j++) o[i][j] = 0.f;
    float m_run[4] = {-1e30f, -1e30f, -1e30f, -1e30f};
    float l_run[4] = {0.f, 0.f, 0.f, 0.f};

    __syncthreads();

    for (int kt = 0; kt <= qt; kt++) {
        // ---- load K tile ----
        const float* kg = g_k + (size_t)(b * SEQ + kt * BKT) * N_EMBD + h * HDIM;
        for (int t = tid; t < BKT * 32; t += 256) {
            int r = t >> 5, c = (t & 31) * 4;
            float4 v = *(const float4*)(kg + (size_t)r * N_EMBD + c);
            float* d = KV + r * KS_STRIDE + c;
            d[0] = v.x; d[1] = v.y; d[2] = v.z; d[3] = v.w;
        }
        __syncthreads();

        // ---- S = Q K^T, 4x4 micro-tile per thread ----
        float s4[4][4];
#pragma unroll
        for (int i = 0; i < 4; i++)
#pragma unroll
            for (int j = 0; j < 4; j++) s4[i][j] = 0.f;

        const float* qr = Qs + (ty * 4) * QS_STRIDE;
        const float* kr = KV + (tx * 4) * KS_STRIDE;
#pragma unroll 4
        for (int kd = 0; kd < HDIM; kd++) {
            float a0 = qr[kd];
            float a1 = qr[QS_STRIDE + kd];
            float a2 = qr[2 * QS_STRIDE + kd];
            float a3 = qr[3 * QS_STRIDE + kd];
            float b0 = kr[kd];
            float b1 = kr[KS_STRIDE + kd];
            float b2 = kr[2 * KS_STRIDE + kd];
            float b3 = kr[3 * KS_STRIDE + kd];
            s4[0][0] = fmaf(a0, b0, s4[0][0]); s4[0][1] = fmaf(a0, b1, s4[0][1]);
            s4[0][2] = fmaf(a0, b2, s4[0][2]); s4[0][3] = fmaf(a0, b3, s4[0][3]);
            s4[1][0] = fmaf(a1, b0, s4[1][0]); s4[1][1] = fmaf(a1, b1, s4[1][1]);
            s4[1][2] = fmaf(a1, b2, s4[1][2]); s4[1][3] = fmaf(a1, b3, s4[1][3]);
            s4[2][0] = fmaf(a2, b0, s4[2][0]); s4[2][1] = fmaf(a2, b1, s4[2][1]);
            s4[2][2] = fmaf(a2, b2, s4[2][2]); s4[2][3] = fmaf(a2, b3, s4[2][3]);
            s4[3][0] = fmaf(a3, b0, s4[3][0]); s4[3][1] = fmaf(a3, b1, s4[3][1]);
            s4[3][2] = fmaf(a3, b2, s4[3][2]); s4[3][3] = fmaf(a3, b3, s4[3][3]);
        }

        // ---- causal mask on diagonal tile ----
        if (kt == qt) {
#pragma unroll
            for (int i = 0; i < 4; i++)
#pragma unroll
                for (int j = 0; j < 4; j++)
                    if (tx * 4 + j > ty * 4 + i) s4[i][j] = -1e30f;
        }

        // ---- online softmax (row stats replicated in regs across 16 lanes) ----
#pragma unroll
        for (int i = 0; i < 4; i++) {
            float mx = fmaxf(fmaxf(s4[i][0], s4[i][1]), fmaxf(s4[i][2], s4[i][3]));
#pragma unroll
            for (int off = 8; off; off >>= 1)
                mx = fmaxf(mx, __shfl_xor_sync(0xffffffffu, mx, off));
            float m2 = fmaxf(m_run[i], mx);
            float sum = 0.f;
#pragma unroll
            for (int j = 0; j < 4; j++) {
                float p = expf(s4[i][j] - m2);
                s4[i][j] = p;
                sum += p;
            }
#pragma unroll
            for (int off = 8; off; off >>= 1)
                sum += __shfl_xor_sync(0xffffffffu, sum, off);
            float sc = expf(m_run[i] - m2);
            l_run[i] = l_run[i] * sc + sum;
            m_run[i] = m2;
#pragma unroll
            for (int j = 0; j < 8; j++) o[i][j] *= sc;
#pragma unroll
            for (int j = 0; j < 4; j++)
                Ps[(ty * 4 + i) * PS_STRIDE + tx * 4 + j] = s4[i][j];
        }
        __syncthreads();   // Ps done; KV free to be overwritten

        // ---- load V tile into shared KV buffer ----
        const float* vg = g_v + (size_t)(b * SEQ + kt * BKT) * N_EMBD + h * HDIM;
        for (int t = tid; t < BKT * 32; t += 256) {
            int r = t >> 5, c = (t & 31) * 4;
            float4 v = *(const float4*)(vg + (size_t)r * N_EMBD + c);
            *(float4*)(KV + r * VS_STRIDE + c) = v;
        }
        __syncthreads();

        // ---- O += P @ V, 4 (rows) x 8 (dims) per thread ----
        const float* pr = Ps + (ty * 4) * PS_STRIDE;
#pragma unroll 2
        for (int kk = 0; kk < BKT; kk++) {
            float p0 = pr[kk];
            float p1 = pr[PS_STRIDE + kk];
            float p2 = pr[2 * PS_STRIDE + kk];
            float p3 = pr[3 * PS_STRIDE + kk];
            float4 v0 = *(const float4*)(KV + kk * VS_STRIDE + tx * 8);
            float4 v1 = *(const float4*)(KV + kk * VS_STRIDE + tx * 8 + 4);
            float vv[8] = {v0.x, v0.y, v0.z, v0.w, v1.x, v1.y, v1.z, v1.w};
#pragma unroll
            for (int j = 0; j < 8; j++) {
                o[0][j] = fmaf(p0, vv[j], o[0][j]);
                o[1][j] = fmaf(p1, vv[j], o[1][j]);
                o[2][j] = fmaf(p2, vv[j], o[2][j]);
                o[3][j] = fmaf(p3, vv[j], o[3][j]);
            }
        }
        __syncthreads();   // protect KV before next K load
    }

    // ---- normalize + write y in [B,S,H*D] layout ----
    float* yg = g_y + (size_t)(b * SEQ + qt * BQ) * N_EMBD + h * HDIM;
#pragma unroll
    for (int i = 0; i < 4; i++) {
        float inv = 1.f / l_run[i];
        float* d = yg + (size_t)(ty * 4 + i) * N_EMBD + tx * 8;
        *(float4*)d       = make_float4(o[i][0] * inv, o[i][1] * inv, o[i][2] * inv, o[i][3] * inv);
        *(float4*)(d + 4) = make_float4(o[i][4] * inv, o[i][5] * inv, o[i][6] * inv, o[i][7] * inv);
    }
}

// =====================================================================
// launch
// =====================================================================
extern "C" void kernel_launch(void* const* d_in, const int* in_sizes, int n_in,
                              void* d_out, int out_size)
{
    const float* x  = (const float*)d_in[0];
    const float* wq = (const float*)d_in[1];
    const float* wk = (const float*)d_in[2];
    const float* wv = (const float*)d_in[3];
    const float* wo = (const float*)d_in[4];
    float* out = (float*)d_out;

    float *pq, *pk, *pv, *py;
    cudaGetSymbolAddress((void**)&pq, g_q);
    cudaGetSymbolAddress((void**)&pk, g_k);
    cudaGetSymbolAddress((void**)&pv, g_v);
    cudaGetSymbolAddress((void**)&py, g_y);

    dim3 gg(N_EMBD / 128, ROWS / 128);   // (16, 32)
    sgemm_kernel<<<gg, 256>>>(x, wq, pq, ROWS, N_EMBD, N_EMBD);
    sgemm_kernel<<<gg, 256>>>(x, wk, pk, ROWS, N_EMBD, N_EMBD);
    sgemm_kernel<<<gg, 256>>>(x, wv, pv, ROWS, N_EMBD, N_EMBD);

    int pairs = ROWS * (N_EMBD / 2);
    rope_kernel<<<(pairs + 255) / 256, 256>>>(pq, pk);

    cudaFuncSetAttribute(attn_kernel, cudaFuncAttributeMaxDynamicSharedMemorySize,
                         ATTN_SMEM_BYTES);
    attn_kernel<<<dim3(SEQ / BQ, NHEAD, BATCH), 256, ATTN_SMEM_BYTES>>>();

    sgemm_kernel<<<gg, 256>>>(py, wo, out, ROWS, N_EMBD, N_EMBD);
}

// round 10
// speedup vs baseline: 1.0071x; 1.0071x over previous
#include <cuda_runtime.h>
#include <math.h>

// ---------------- problem constants ----------------
constexpr int N_EMBD = 2048;
constexpr int NHEAD  = 16;
constexpr int HDIM   = 128;
constexpr int BATCH  = 2;
constexpr int SEQ    = 2048;
constexpr int ROWS   = BATCH * SEQ;   // 4096

// ---------------- scratch (device globals: no allocs allowed) ----------------
__device__ float g_q[ROWS * N_EMBD];
__device__ float g_k[ROWS * N_EMBD];
__device__ float g_v[ROWS * N_EMBD];
__device__ float g_y[ROWS * N_EMBD];

// =====================================================================
// SGEMM: C[M,N] = A[M,K] @ B[K,N], all row-major, M,N,K % 128 == 0
// 128x128 block tile, BK=8, 256 threads, 8x8 register micro-tile.
// =====================================================================
__global__ __launch_bounds__(256) void sgemm_kernel(
    const float* __restrict__ A, const float* __restrict__ B,
    float* __restrict__ C, int M, int N, int K)
{
    __shared__ float As[8][128];   // As[k][m] (transposed A tile)
    __shared__ float Bs[8][132];   // Bs[k][n] (padded)

    const int tid  = threadIdx.x;
    const int row0 = blockIdx.y * 128;
    const int col0 = blockIdx.x * 128;

    const int aRow = tid >> 1;          // 0..127
    const int aCol = (tid & 1) * 4;     // 0 or 4
    const int bRow = tid >> 5;          // 0..7
    const int bCol = (tid & 31) * 4;    // 0..124

    const int tx = tid & 15;
    const int ty = tid >> 4;

    float acc[8][8];
#pragma unroll
    for (int i = 0; i < 8; i++)
#pragma unroll
        for (int j = 0; j < 8; j++) acc[i][j] = 0.f;

    const float* Ap = A + (size_t)(row0 + aRow) * K + aCol;
    const float* Bp = B + (size_t)col0 + bCol;

    for (int k0 = 0; k0 < K; k0 += 8) {
        float4 av = *(const float4*)(Ap + k0);
        float4 bv = *(const float4*)(Bp + (size_t)(k0 + bRow) * N);
        __syncthreads();
        As[aCol + 0][aRow] = av.x;
        As[aCol + 1][aRow] = av.y;
        As[aCol + 2][aRow] = av.z;
        As[aCol + 3][aRow] = av.w;
        *(float4*)&Bs[bRow][bCol] = bv;
        __syncthreads();

#pragma unroll
        for (int kk = 0; kk < 8; kk++) {
            float4 a0 = *(const float4*)&As[kk][ty * 8];
            float4 a1 = *(const float4*)&As[kk][ty * 8 + 4];
            float4 b0 = *(const float4*)&Bs[kk][tx * 8];
            float4 b1 = *(const float4*)&Bs[kk][tx * 8 + 4];
            float a[8] = {a0.x, a0.y, a0.z, a0.w, a1.x, a1.y, a1.z, a1.w};
            float b[8] = {b0.x, b0.y, b0.z, b0.w, b1.x, b1.y, b1.z, b1.w};
#pragma unroll
            for (int i = 0; i < 8; i++)
#pragma unroll
                for (int j = 0; j < 8; j++)
                    acc[i][j] = fmaf(a[i], b[j], acc[i][j]);
        }
    }

#pragma unroll
    for (int i = 0; i < 8; i++) {
        float* Cp = C + (size_t)(row0 + ty * 8 + i) * N + col0 + tx * 8;
        *(float4*)Cp       = make_float4(acc[i][0], acc[i][1], acc[i][2], acc[i][3]);
        *(float4*)(Cp + 4) = make_float4(acc[i][4], acc[i][5], acc[i][6], acc[i][7]);
    }
}

// =====================================================================
// RoPE (interleaved pairs, applied in-place to q and k)
// =====================================================================
__global__ void rope_kernel(float* __restrict__ q, float* __restrict__ k)
{
    int idx = blockIdx.x * blockDim.x + threadIdx.x;
    if (idx >= ROWS * (N_EMBD / 2)) return;
    int row = idx >> 10;            // 1024 pairs per row
    int p   = idx & 1023;           // pair index in row: h*64 + i
    int i   = p & 63;               // pair within head
    int s   = row & (SEQ - 1);      // sequence position

    // inv_freq = 10000^(-i/64) ; ln(10000)/64 = 0.14391156831212787
    float inv = expf(-(float)i * 0.14391156831212787f);
    float ang = (float)s * inv;
    float sn, c;
    sincosf(ang, &sn, &c);

    int base = row * N_EMBD + (p << 1);
    float q1 = q[base], q2 = q[base + 1];
    q[base]     = q1 * c - q2 * sn;
    q[base + 1] = q1 * sn + q2 * c;
    float k1 = k[base], k2 = k[base + 1];
    k[base]     = k1 * c - k2 * sn;
    k[base + 1] = k1 * sn + k2 * c;
}

// =====================================================================
// Fused causal attention (flash-style, fp32).
// Block = 256 threads handles one (b, h, 64-query tile).
// Online softmax stats kept in registers (each row owned by 16 lanes).
// K and V share one smem buffer (loaded sequentially per key tile).
// =====================================================================
constexpr int BQ = 64, BKT = 64;
constexpr int QS_STRIDE = 129;   // odd-mod-8 stride -> low LDS conflicts for column reads
constexpr int KS_STRIDE = 129;
constexpr int VS_STRIDE = 132;   // float4-aligned rows
constexpr int PS_STRIDE = 65;
constexpr int ATTN_SMEM_FLOATS = BQ * QS_STRIDE + BQ * VS_STRIDE + BQ * PS_STRIDE;
constexpr int ATTN_SMEM_BYTES  = ATTN_SMEM_FLOATS * 4;   // 83456 B

__global__ __launch_bounds__(256) void attn_kernel()
{
    extern __shared__ float sm[];
    float* Qs = sm;
    float* KV = Qs + BQ * QS_STRIDE;
    float* Ps = KV + BQ * VS_STRIDE;

    const int qt = blockIdx.x, h = blockIdx.y, b = blockIdx.z;
    const int tid = threadIdx.x;
    const int tx = tid & 15;    // 16 lanes share a row group
    const int ty = tid >> 4;    // owns query rows ty*4 .. ty*4+3
    const float scale = 0.08838834764831845f;  // 1/sqrt(128)

    // load Q tile (pre-scaled)
    const float* qg = g_q + (size_t)(b * SEQ + qt * BQ) * N_EMBD + h * HDIM;
    for (int t = tid; t < BQ * 32; t += 256) {
        int r = t >> 5, c = (t & 31) * 4;
        float4 v = *(const float4*)(qg + (size_t)r * N_EMBD + c);
        float* d = Qs + r * QS_STRIDE + c;
        d[0] = v.x * scale; d[1] = v.y * scale; d[2] = v.z * scale; d[3] = v.w * scale;
    }

    float o[4][8];
#pragma unroll
    for (int i = 0; i < 4; i++)
#pragma unroll
        for (int j = 0; j < 8; j++) o[i][j] = 0.f;
    float m_run[4] = {-1e30f, -1e30f, -1e30f, -1e30f};
    float l_run[4] = {0.f, 0.f, 0.f, 0.f};

    __syncthreads();

    for (int kt = 0; kt <= qt; kt++) {
        // ---- load K tile ----
        const float* kg = g_k + (size_t)(b * SEQ + kt * BKT) * N_EMBD + h * HDIM;
        for (int t = tid; t < BKT * 32; t += 256) {
            int r = t >> 5, c = (t & 31) * 4;
            float4 v = *(const float4*)(kg + (size_t)r * N_EMBD + c);
            float* d = KV + r * KS_STRIDE + c;
            d[0] = v.x; d[1] = v.y; d[2] = v.z; d[3] = v.w;
        }
        __syncthreads();

        // ---- S = Q K^T, 4x4 micro-tile per thread ----
        float s4[4][4];
#pragma unroll
        for (int i = 0; i < 4; i++)
#pragma unroll
            for (int j = 0; j < 4; j++) s4[i][j] = 0.f;

        const float* qr = Qs + (ty * 4) * QS_STRIDE;
        const float* kr = KV + (tx * 4) * KS_STRIDE;
#pragma unroll 4
        for (int kd = 0; kd < HDIM; kd++) {
            float a0 = qr[kd];
            float a1 = qr[QS_STRIDE + kd];
            float a2 = qr[2 * QS_STRIDE + kd];
            float a3 = qr[3 * QS_STRIDE + kd];
            float b0 = kr[kd];
            float b1 = kr[KS_STRIDE + kd];
            float b2 = kr[2 * KS_STRIDE + kd];
            float b3 = kr[3 * KS_STRIDE + kd];
            s4[0][0] = fmaf(a0, b0, s4[0][0]); s4[0][1] = fmaf(a0, b1, s4[0][1]);
            s4[0][2] = fmaf(a0, b2, s4[0][2]); s4[0][3] = fmaf(a0, b3, s4[0][3]);
            s4[1][0] = fmaf(a1, b0, s4[1][0]); s4[1][1] = fmaf(a1, b1, s4[1][1]);
            s4[1][2] = fmaf(a1, b2, s4[1][2]); s4[1][3] = fmaf(a1, b3, s4[1][3]);
            s4[2][0] = fmaf(a2, b0, s4[2][0]); s4[2][1] = fmaf(a2, b1, s4[2][1]);
            s4[2][2] = fmaf(a2, b2, s4[2][2]); s4[2][3] = fmaf(a2, b3, s4[2][3]);
            s4[3][0] = fmaf(a3, b0, s4[3][0]); s4[3][1] = fmaf(a3, b1, s4[3][1]);
            s4[3][2] = fmaf(a3, b2, s4[3][2]); s4[3][3] = fmaf(a3, b3, s4[3][3]);
        }

        // ---- causal mask on diagonal tile ----
        if (kt == qt) {
#pragma unroll
            for (int i = 0; i < 4; i++)
#pragma unroll
                for (int j = 0; j < 4; j++)
                    if (tx * 4 + j > ty * 4 + i) s4[i][j] = -1e30f;
        }

        // ---- online softmax (row stats replicated in regs across 16 lanes) ----
#pragma unroll
        for (int i = 0; i < 4; i++) {
            float mx = fmaxf(fmaxf(s4[i][0], s4[i][1]), fmaxf(s4[i][2], s4[i][3]));
#pragma unroll
            for (int off = 8; off; off >>= 1)
                mx = fmaxf(mx, __shfl_xor_sync(0xffffffffu, mx, off));
            float m2 = fmaxf(m_run[i], mx);
            float sum = 0.f;
#pragma unroll
            for (int j = 0; j < 4; j++) {
                float p = expf(s4[i][j] - m2);
                s4[i][j] = p;
                sum += p;
            }
#pragma unroll
            for (int off = 8; off; off >>= 1)
                sum += __shfl_xor_sync(0xffffffffu, sum, off);
            float sc = expf(m_run[i] - m2);
            l_run[i] = l_run[i] * sc + sum;
            m_run[i] = m2;
#pragma unroll
            for (int j = 0; j < 8; j++) o[i][j] *= sc;
#pragma unroll
            for (int j = 0; j < 4; j++)
                Ps[(ty * 4 + i) * PS_STRIDE + tx * 4 + j] = s4[i][j];
        }
        __syncthreads();   // Ps done; KV free to be overwritten

        // ---- load V tile into shared KV buffer ----
        const float* vg = g_v + (size_t)(b * SEQ + kt * BKT) * N_EMBD + h * HDIM;
        for (int t = tid; t < BKT * 32; t += 256) {
            int r = t >> 5, c = (t & 31) * 4;
            float4 v = *(const float4*)(vg + (size_t)r * N_EMBD + c);
            *(float4*)(KV + r * VS_STRIDE + c) = v;
        }
        __syncthreads();

        // ---- O += P @ V, 4 (rows) x 8 (dims) per thread ----
        const float* pr = Ps + (ty * 4) * PS_STRIDE;
#pragma unroll 2
        for (int kk = 0; kk < BKT; kk++) {
            float p0 = pr[kk];
            float p1 = pr[PS_STRIDE + kk];
            float p2 = pr[2 * PS_STRIDE + kk];
            float p3 = pr[3 * PS_STRIDE + kk];
            float4 v0 = *(const float4*)(KV + kk * VS_STRIDE + tx * 8);
            float4 v1 = *(const float4*)(KV + kk * VS_STRIDE + tx * 8 + 4);
            float vv[8] = {v0.x, v0.y, v0.z, v0.w, v1.x, v1.y, v1.z, v1.w};
#pragma unroll
            for (int j = 0; j < 8; j++) {
                o[0][j] = fmaf(p0, vv[j], o[0][j]);
                o[1][j] = fmaf(p1, vv[j], o[1][j]);
                o[2][j] = fmaf(p2, vv[j], o[2][j]);
                o[3][j] = fmaf(p3, vv[j], o[3][j]);
            }
        }
        __syncthreads();   // protect KV before next K load
    }

    // ---- normalize + write y in [B,S,H*D] layout ----
    float* yg = g_y + (size_t)(b * SEQ + qt * BQ) * N_EMBD + h * HDIM;
#pragma unroll
    for (int i = 0; i < 4; i++) {
        float inv = 1.f / l_run[i];
        float* d = yg + (size_t)(ty * 4 + i) * N_EMBD + tx * 8;
        *(float4*)d       = make_float4(o[i][0] * inv, o[i][1] * inv, o[i][2] * inv, o[i][3] * inv);
        *(float4*)(d + 4) = make_float4(o[i][4] * inv, o[i][5] * inv, o[i][6] * inv, o[i][7] * inv);
    }
}

// =====================================================================
// launch
// =====================================================================
extern "C" void kernel_launch(void* const* d_in, const int* in_sizes, int n_in,
                              void* d_out, int out_size)
{
    const float* x  = (const float*)d_in[0];
    const float* wq = (const float*)d_in[1];
    const float* wk = (const float*)d_in[2];
    const float* wv = (const float*)d_in[3];
    const float* wo = (const float*)d_in[4];
    float* out = (float*)d_out;

    float *pq, *pk, *pv, *py;
    cudaGetSymbolAddress((void**)&pq, g_q);
    cudaGetSymbolAddress((void**)&pk, g_k);
    cudaGetSymbolAddress((void**)&pv, g_v);
    cudaGetSymbolAddress((void**)&py, g_y);

    dim3 gg(N_EMBD / 128, ROWS / 128);   // (16, 32)
    sgemm_kernel<<<gg, 256>>>(x, wq, pq, ROWS, N_EMBD, N_EMBD);
    sgemm_kernel<<<gg, 256>>>(x, wk, pk, ROWS, N_EMBD, N_EMBD);
    sgemm_kernel<<<gg, 256>>>(x, wv, pv, ROWS, N_EMBD, N_EMBD);

    int pairs = ROWS * (N_EMBD / 2);
    rope_kernel<<<(pairs + 255) / 256, 256>>>(pq, pk);

    cudaFuncSetAttribute(attn_kernel, cudaFuncAttributeMaxDynamicSharedMemorySize,
                         ATTN_SMEM_BYTES);
    attn_kernel<<<dim3(SEQ / BQ, NHEAD, BATCH), 256, ATTN_SMEM_BYTES>>>();

    sgemm_kernel<<<gg, 256>>>(py, wo, out, ROWS, N_EMBD, N_EMBD);
}